// round 8
// baseline (speedup 1.0000x reference)
#include <cuda_runtime.h>
#include <cuda_fp16.h>
#include <cstdint>

// ---------------------------------------------------------------------------
// Problem constants
// ---------------------------------------------------------------------------
#define B_  32
#define D_  3
#define T_  16384
#define S_  128
#define L_  16
#define H_  512
#define C_  10
#define TP  16369          // T - L + 1 valid positions
#define SHN 48             // D*L = K (3 k-steps of 16)

#define NT      128        // positions per block tile (GEMM N-tile)
#define NTILES  (B_ * (T_ / NT))   // 4096
#define THR     256
#define GRID    296        // 2 blocks / SM, all co-resident (launch_bounds)
#define XT_W    (NT + L_)  // 144 elements per x row in tile

#define INF_F __int_as_float(0x7F800000)

// grid-barrier counter: monotonically increasing across graph replays.
// phase = old/GRID identifies this launch's barrier instance.
__device__ unsigned long long g_bar;

// ---------------------------------------------------------------------------
// D(16x8) += A(16x16,row) * B(16x8,col)   f16 x f16 -> f32
__device__ __forceinline__ void mma16(float* d, uint32_t a0, uint32_t a1,
                                      uint32_t a2, uint32_t a3,
                                      uint32_t b0, uint32_t b1) {
    asm volatile(
        "mma.sync.aligned.m16n8k16.row.col.f32.f16.f16.f32 "
        "{%0,%1,%2,%3}, {%4,%5,%6,%7}, {%8,%9}, {%0,%1,%2,%3};"
        : "+f"(d[0]), "+f"(d[1]), "+f"(d[2]), "+f"(d[3])
        : "r"(a0), "r"(a1), "r"(a2), "r"(a3), "r"(b0), "r"(b1));
}

__device__ __forceinline__ uint32_t packh2(float lo, float hi) {
    __half2 h = __floats2half2_rn(lo, hi);
    return *reinterpret_cast<uint32_t*>(&h);
}

// ---------------------------------------------------------------------------
// Kernel: persistent fp16-MMA shapelet distance + fused MLP (post grid-sync)
// ---------------------------------------------------------------------------
__global__ __launch_bounds__(THR, 2) void dist_kernel(
    const float* __restrict__ x,
    const float* __restrict__ shg,
    const float* __restrict__ W1,
    const float* __restrict__ b1,
    const float* __restrict__ W2,
    const float* __restrict__ b2,
    float* __restrict__ out_dist,
    float* __restrict__ out_cls)
{
    __shared__ float  xs[D_ * XT_W];        // raw fp32 (for exact wsq)
    __shared__ __half hA[D_ * XT_W];        // hA[i] = f16(x[i])   (even-pair copy)
    __shared__ __half hB[D_ * XT_W];        // hB[i] = f16(x[i+1]) (odd-pair copy)
    __shared__ float  swsq[NT];
    __shared__ float  sssq[S_];
    __shared__ int    sdmin[S_];
    __shared__ float  hs[H_];               // MLP hidden (post-barrier phase)
    __shared__ unsigned long long s_old;

    const int tid  = threadIdx.x;
    const int wid  = tid >> 5;
    const int lane = tid & 31;
    const int q    = lane >> 2;      // groupID
    const int r    = lane & 3;       // threadID_in_group

    const int mbase = (wid & 3) * 32;       // warp's 32 M-rows
    const int nbase = (wid >> 2) * 64;      // warp's 64 N-cols

    // --- one-time: exact fp32 shapelet squared norms; A fragments -> regs ---
    if (tid < S_) {
        const float* srow = shg + tid * SHN;
        float ssq = 0.f;
        #pragma unroll
        for (int k = 0; k < SHN; ++k) ssq = fmaf(srow[k], srow[k], ssq);
        sssq[tid] = ssq;
        sdmin[tid] = 0x7F800000;
    }

    // A fragments: afr[ks][mt][4]; k = ks*16 + kk
    uint32_t afr[3][2][4];
    #pragma unroll
    for (int ks = 0; ks < 3; ++ks) {
        #pragma unroll
        for (int mt = 0; mt < 2; ++mt) {
            const int r0 = mbase + mt * 16 + q;       // row for a0/a2
            const int r1 = r0 + 8;                    // row for a1/a3
            const int k0 = ks * 16 + 2 * r;
            const float* p0 = shg + r0 * SHN + k0;
            const float* p1 = shg + r1 * SHN + k0;
            afr[ks][mt][0] = packh2(-2.f * p0[0], -2.f * p0[1]);
            afr[ks][mt][1] = packh2(-2.f * p1[0], -2.f * p1[1]);
            afr[ks][mt][2] = packh2(-2.f * p0[8], -2.f * p0[9]);
            afr[ks][mt][3] = packh2(-2.f * p1[8], -2.f * p1[9]);
        }
    }
    __syncthreads();

    const uint32_t* hA32 = reinterpret_cast<const uint32_t*>(hA);
    const uint32_t* hB32 = reinterpret_cast<const uint32_t*>(hB);
    const uint32_t* hw = (q & 1) ? hB32 : hA32;
    const int lane_off = q + 2 * r - (q & 1);

    for (int tile = blockIdx.x; tile < NTILES; tile += GRID) {
        const int b     = tile >> 7;                  // 128 tiles / batch
        const int tbase = (tile & 127) * NT;
        const float* xb = x + (size_t)b * D_ * T_;

        // ---- phase 1: load x tile (fp32 + two fp16 copies) ----
        {
            const int idx4 = tid;                     // 108 float4 total
            if (idx4 < (D_ * XT_W) / 4) {
                const int d = idx4 / (XT_W / 4);
                const int j = (idx4 % (XT_W / 4)) * 4;
                const int g = tbase + j;
                float4 v;
                if (g + 3 < T_) {
                    v = *reinterpret_cast<const float4*>(xb + d * T_ + g);
                } else {
                    v.x = (g     < T_) ? xb[d*T_ + g]     : 0.f;
                    v.y = (g + 1 < T_) ? xb[d*T_ + g + 1] : 0.f;
                    v.z = (g + 2 < T_) ? xb[d*T_ + g + 2] : 0.f;
                    v.w = (g + 3 < T_) ? xb[d*T_ + g + 3] : 0.f;
                }
                *reinterpret_cast<float4*>(&xs[d * XT_W + j]) = v;
                const int hi = d * XT_W + j;
                *reinterpret_cast<uint32_t*>(&hA[hi])     = packh2(v.x, v.y);
                *reinterpret_cast<uint32_t*>(&hA[hi + 2]) = packh2(v.z, v.w);
                if (j > 0) hB[hi - 1] = __float2half(v.x);
                hB[hi    ] = __float2half(v.y);
                hB[hi + 1] = __float2half(v.z);
                hB[hi + 2] = __float2half(v.w);
            }
        }
        __syncthreads();

        // ---- phase 2: wsq from raw fp32, poison invalid tail ----
        if (tid < NT) {
            float w0 = 0.f, w1 = 0.f, w2 = 0.f;
            #pragma unroll
            for (int l = 0; l < L_; ++l) {
                const float v0 = xs[0 * XT_W + tid + l];
                const float v1 = xs[1 * XT_W + tid + l];
                const float v2 = xs[2 * XT_W + tid + l];
                w0 = fmaf(v0, v0, w0);
                w1 = fmaf(v1, v1, w1);
                w2 = fmaf(v2, v2, w2);
            }
            swsq[tid] = (tbase + tid < TP) ? (w0 + w1 + w2) : INF_F;
        }

        // ---- phase 3: MMA, warp tile 32M x 64N, K=48 (3 k-steps) ----
        float acc[2][8][4];
        #pragma unroll
        for (int mt = 0; mt < 2; ++mt)
            #pragma unroll
            for (int nt = 0; nt < 8; ++nt)
                #pragma unroll
                for (int e = 0; e < 4; ++e) acc[mt][nt][e] = 0.f;

        #pragma unroll
        for (int ks = 0; ks < 3; ++ks) {
            const int base = (ks * XT_W + nbase + lane_off) >> 1;
            #pragma unroll
            for (int nt = 0; nt < 8; ++nt) {
                const uint32_t b0 = hw[base + nt * 4];
                const uint32_t b1 = hw[base + nt * 4 + 4];
                mma16(acc[0][nt], afr[ks][0][0], afr[ks][0][1],
                                  afr[ks][0][2], afr[ks][0][3], b0, b1);
                mma16(acc[1][nt], afr[ks][1][0], afr[ks][1][1],
                                  afr[ks][1][2], afr[ks][1][3], b0, b1);
            }
        }
        __syncthreads();   // swsq ready

        // ---- phase 4: dist = min_n(acc + wsq[n]); smem atomic min ----
        float wq[8][2];
        #pragma unroll
        for (int nt = 0; nt < 8; ++nt) {
            wq[nt][0] = swsq[nbase + nt * 8 + r * 2    ];
            wq[nt][1] = swsq[nbase + nt * 8 + r * 2 + 1];
        }
        float rmin[2][2];
        #pragma unroll
        for (int mt = 0; mt < 2; ++mt)
            #pragma unroll
            for (int h = 0; h < 2; ++h) {
                float m = INF_F;
                #pragma unroll
                for (int nt = 0; nt < 8; ++nt) {
                    m = fminf(m, acc[mt][nt][h * 2    ] + wq[nt][0]);
                    m = fminf(m, acc[mt][nt][h * 2 + 1] + wq[nt][1]);
                }
                rmin[mt][h] = m;
            }
        #pragma unroll
        for (int mt = 0; mt < 2; ++mt)
            #pragma unroll
            for (int h = 0; h < 2; ++h) {
                float v = rmin[mt][h];
                v = fminf(v, __shfl_xor_sync(0xffffffffu, v, 1));
                v = fminf(v, __shfl_xor_sync(0xffffffffu, v, 2));
                rmin[mt][h] = v;
            }
        if (r == 0) {
            #pragma unroll
            for (int mt = 0; mt < 2; ++mt)
                #pragma unroll
                for (int h = 0; h < 2; ++h) {
                    const int row = mbase + mt * 16 + h * 8 + q;
                    const float v = rmin[mt][h] + sssq[row];
                    atomicMin(&sdmin[row], __float_as_int(v));
                }
        }
        __syncthreads();

        // ---- phase 5: fold into global; reset own slot ----
        if (tid < S_) {
            const int v = sdmin[tid];
            atomicMin(reinterpret_cast<int*>(out_dist) + b * S_ + tid, v);
            sdmin[tid] = 0x7F800000;
        }
    }

    // ================= grid barrier (all 296 blocks co-resident) ============
    __threadfence();
    if (tid == 0) s_old = atomicAdd(&g_bar, 1ULL);
    __syncthreads();
    {
        const unsigned long long target =
            (s_old / (unsigned long long)GRID + 1ULL) * (unsigned long long)GRID;
        if (tid == 0) {
            while (*(volatile unsigned long long*)&g_bar < target) { }
        }
    }
    __syncthreads();
    __threadfence();

    // ================= fused MLP: blocks 0..31, one batch each ==============
    if (blockIdx.x >= B_) return;
    const int b = blockIdx.x;

    // lane-resident distance float4 (global is L2-hot)
    const float4 d4 = reinterpret_cast<const float4*>(out_dist + b * S_)[lane];

    // Layer 1: warp w computes neurons [w*64, w*64+64); coalesced LDG.128 rows
    #pragma unroll 4
    for (int i = 0; i < 64; ++i) {
        const int h = wid * 64 + i;
        const float4 w4 = reinterpret_cast<const float4*>(W1 + h * S_)[lane];
        float acc = d4.x * w4.x;
        acc = fmaf(d4.y, w4.y, acc);
        acc = fmaf(d4.z, w4.z, acc);
        acc = fmaf(d4.w, w4.w, acc);
        #pragma unroll
        for (int off = 16; off > 0; off >>= 1)
            acc += __shfl_xor_sync(0xffffffffu, acc, off);
        if (lane == 0) hs[h] = fmaxf(acc + b1[h], 0.f);
    }
    __syncthreads();

    // Layer 2: warps cover classes round-robin (8 warps, 10 classes)
    for (int c = wid; c < C_; c += 8) {
        const float4* w4p = reinterpret_cast<const float4*>(W2 + c * H_);
        const float4* h4p = reinterpret_cast<const float4*>(hs);
        float acc = 0.f;
        #pragma unroll
        for (int j = 0; j < H_ / (32 * 4); ++j) {       // 4 iterations
            const float4 w4 = w4p[lane + j * 32];
            const float4 h4 = h4p[lane + j * 32];
            acc = fmaf(w4.x, h4.x, acc);
            acc = fmaf(w4.y, h4.y, acc);
            acc = fmaf(w4.z, h4.z, acc);
            acc = fmaf(w4.w, h4.w, acc);
        }
        #pragma unroll
        for (int off = 16; off > 0; off >>= 1)
            acc += __shfl_xor_sync(0xffffffffu, acc, off);
        if (lane == 0) out_cls[b * C_ + c] = acc + b2[c];
    }
}

// ---------------------------------------------------------------------------
extern "C" void kernel_launch(void* const* d_in, const int* in_sizes, int n_in,
                              void* d_out, int out_size)
{
    const float* x  = (const float*)d_in[0];
    const float* sh = (const float*)d_in[1];
    const float* W1 = (const float*)d_in[2];
    const float* b1 = (const float*)d_in[3];
    const float* W2 = (const float*)d_in[4];
    const float* b2 = (const float*)d_in[5];

    float* out_dist = (float*)d_out;
    float* out_cls  = (float*)d_out + B_ * S_;

    // init distances to a huge positive sentinel (0x7f7f7f7f ~ 3.39e38)
    cudaMemsetAsync(out_dist, 0x7f, B_ * S_ * sizeof(float), 0);

    dist_kernel<<<GRID, THR>>>(x, sh, W1, b1, W2, b2, out_dist, out_cls);
}

// round 9
// speedup vs baseline: 1.0853x; 1.0853x over previous
#include <cuda_runtime.h>
#include <cuda_fp16.h>
#include <cstdint>

// ---------------------------------------------------------------------------
// Problem constants
// ---------------------------------------------------------------------------
#define B_  32
#define D_  3
#define T_  16384
#define S_  128
#define L_  16
#define H_  512
#define C_  10
#define TP  16369          // T - L + 1 valid positions
#define SHN 48             // D*L = K (3 k-steps of 16)

#define NT      256        // positions per block tile (two 128-col MMA halves)
#define NTILES  (B_ * (T_ / NT))   // 2048
#define THR     256
#define GRID    293        // ceil(2048/7): balanced 7 tiles/block, 1 wave
#define XT_W    (NT + L_)  // 272 elements per x row in tile

#define INF_F __int_as_float(0x7F800000)

// ---------------------------------------------------------------------------
// D(16x8) += A(16x16,row) * B(16x8,col)   f16 x f16 -> f32
__device__ __forceinline__ void mma16(float* d, uint32_t a0, uint32_t a1,
                                      uint32_t a2, uint32_t a3,
                                      uint32_t b0, uint32_t b1) {
    asm volatile(
        "mma.sync.aligned.m16n8k16.row.col.f32.f16.f16.f32 "
        "{%0,%1,%2,%3}, {%4,%5,%6,%7}, {%8,%9}, {%0,%1,%2,%3};"
        : "+f"(d[0]), "+f"(d[1]), "+f"(d[2]), "+f"(d[3])
        : "r"(a0), "r"(a1), "r"(a2), "r"(a3), "r"(b0), "r"(b1));
}

__device__ __forceinline__ uint32_t packh2(float lo, float hi) {
    __half2 h = __floats2half2_rn(lo, hi);
    return *reinterpret_cast<uint32_t*>(&h);
}

// ---------------------------------------------------------------------------
// Kernel 1: persistent fp16-MMA shapelet distance (256-pos tiles, 2 halves)
// ---------------------------------------------------------------------------
__global__ __launch_bounds__(THR, 2) void dist_kernel(
    const float* __restrict__ x,
    const float* __restrict__ shg,
    float* __restrict__ out_dist)
{
    __shared__ float  xs[D_ * XT_W];        // raw fp32 (for exact wsq)
    __shared__ __half hA[D_ * XT_W];        // hA[i] = f16(x[i])   (even-pair copy)
    __shared__ __half hB[D_ * XT_W];        // hB[i] = f16(x[i+1]) (odd-pair copy)
    __shared__ float  swsq[NT];
    __shared__ float  sssq[S_];
    __shared__ int    sdmin[S_];

    const int tid  = threadIdx.x;
    const int wid  = tid >> 5;
    const int lane = tid & 31;
    const int q    = lane >> 2;      // groupID
    const int r    = lane & 3;       // threadID_in_group

    const int mbase = (wid & 3) * 32;       // warp's 32 M-rows
    const int nbase = (wid >> 2) * 64;      // warp's 64 N-cols (per half)

    // --- one-time: exact fp32 shapelet squared norms; A fragments -> regs ---
    if (tid < S_) {
        const float* srow = shg + tid * SHN;
        float ssq = 0.f;
        #pragma unroll
        for (int k = 0; k < SHN; ++k) ssq = fmaf(srow[k], srow[k], ssq);
        sssq[tid] = ssq;
        sdmin[tid] = 0x7F800000;
    }

    // A fragments: afr[ks][mt][4]; k = ks*16 + kk  (tile-invariant)
    uint32_t afr[3][2][4];
    #pragma unroll
    for (int ks = 0; ks < 3; ++ks) {
        #pragma unroll
        for (int mt = 0; mt < 2; ++mt) {
            const int r0 = mbase + mt * 16 + q;       // row for a0/a2
            const int r1 = r0 + 8;                    // row for a1/a3
            const int k0 = ks * 16 + 2 * r;
            const float* p0 = shg + r0 * SHN + k0;
            const float* p1 = shg + r1 * SHN + k0;
            afr[ks][mt][0] = packh2(-2.f * p0[0], -2.f * p0[1]);
            afr[ks][mt][1] = packh2(-2.f * p1[0], -2.f * p1[1]);
            afr[ks][mt][2] = packh2(-2.f * p0[8], -2.f * p0[9]);
            afr[ks][mt][3] = packh2(-2.f * p1[8], -2.f * p1[9]);
        }
    }
    __syncthreads();

    const uint32_t* hA32 = reinterpret_cast<const uint32_t*>(hA);
    const uint32_t* hB32 = reinterpret_cast<const uint32_t*>(hB);
    const uint32_t* hw = (q & 1) ? hB32 : hA32;
    const int lane_off = q + 2 * r - (q & 1);

    for (int tile = blockIdx.x; tile < NTILES; tile += GRID) {
        const int b     = tile >> 6;                  // 64 tiles / batch
        const int tbase = (tile & 63) * NT;
        const float* xb = x + (size_t)b * D_ * T_;

        // ---- phase 1: load x tile (fp32 + two fp16 copies), 204 float4 ----
        {
            const int idx4 = tid;
            if (idx4 < (D_ * XT_W) / 4) {             // 204
                const int d = idx4 / (XT_W / 4);      // XT_W/4 = 68
                const int j = (idx4 % (XT_W / 4)) * 4;
                const int g = tbase + j;
                float4 v;
                if (g + 3 < T_) {
                    v = *reinterpret_cast<const float4*>(xb + d * T_ + g);
                } else {
                    v.x = (g     < T_) ? xb[d*T_ + g]     : 0.f;
                    v.y = (g + 1 < T_) ? xb[d*T_ + g + 1] : 0.f;
                    v.z = (g + 2 < T_) ? xb[d*T_ + g + 2] : 0.f;
                    v.w = (g + 3 < T_) ? xb[d*T_ + g + 3] : 0.f;
                }
                *reinterpret_cast<float4*>(&xs[d * XT_W + j]) = v;
                const int hi = d * XT_W + j;
                *reinterpret_cast<uint32_t*>(&hA[hi])     = packh2(v.x, v.y);
                *reinterpret_cast<uint32_t*>(&hA[hi + 2]) = packh2(v.z, v.w);
                if (j > 0) hB[hi - 1] = __float2half(v.x);
                hB[hi    ] = __float2half(v.y);
                hB[hi + 1] = __float2half(v.z);
                hB[hi + 2] = __float2half(v.w);
            }
        }
        __syncthreads();

        // ---- phase 2: wsq, one position per thread (all 256) ----
        {
            float w0 = 0.f, w1 = 0.f, w2 = 0.f;
            #pragma unroll
            for (int l = 0; l < L_; ++l) {
                const float v0 = xs[0 * XT_W + tid + l];
                const float v1 = xs[1 * XT_W + tid + l];
                const float v2 = xs[2 * XT_W + tid + l];
                w0 = fmaf(v0, v0, w0);
                w1 = fmaf(v1, v1, w1);
                w2 = fmaf(v2, v2, w2);
            }
            swsq[tid] = (tbase + tid < TP) ? (w0 + w1 + w2) : INF_F;
        }
        __syncthreads();   // wsq ready for all epilogue readers

        // ---- phases 3+4: two N-halves of MMA + local epilogue ----
        float rmin[2][2];
        #pragma unroll
        for (int mt = 0; mt < 2; ++mt)
            #pragma unroll
            for (int h = 0; h < 2; ++h) rmin[mt][h] = INF_F;

        #pragma unroll
        for (int half = 0; half < 2; ++half) {
            const int nbh = half * 128 + nbase;

            float acc[2][8][4];
            #pragma unroll
            for (int mt = 0; mt < 2; ++mt)
                #pragma unroll
                for (int nt = 0; nt < 8; ++nt)
                    #pragma unroll
                    for (int e = 0; e < 4; ++e) acc[mt][nt][e] = 0.f;

            #pragma unroll
            for (int ks = 0; ks < 3; ++ks) {
                const int base = (ks * XT_W + nbh + lane_off) >> 1;
                #pragma unroll
                for (int nt = 0; nt < 8; ++nt) {
                    const uint32_t b0 = hw[base + nt * 4];
                    const uint32_t b1 = hw[base + nt * 4 + 4];
                    mma16(acc[0][nt], afr[ks][0][0], afr[ks][0][1],
                                      afr[ks][0][2], afr[ks][0][3], b0, b1);
                    mma16(acc[1][nt], afr[ks][1][0], afr[ks][1][1],
                                      afr[ks][1][2], afr[ks][1][3], b0, b1);
                }
            }

            float wq[8][2];
            #pragma unroll
            for (int nt = 0; nt < 8; ++nt) {
                wq[nt][0] = swsq[nbh + nt * 8 + r * 2    ];
                wq[nt][1] = swsq[nbh + nt * 8 + r * 2 + 1];
            }
            #pragma unroll
            for (int mt = 0; mt < 2; ++mt)
                #pragma unroll
                for (int h = 0; h < 2; ++h) {
                    float m = rmin[mt][h];
                    #pragma unroll
                    for (int nt = 0; nt < 8; ++nt) {
                        m = fminf(m, acc[mt][nt][h * 2    ] + wq[nt][0]);
                        m = fminf(m, acc[mt][nt][h * 2 + 1] + wq[nt][1]);
                    }
                    rmin[mt][h] = m;
                }
        }

        // ---- reduce: quad shfl + smem atomic (once per 256 positions) ----
        #pragma unroll
        for (int mt = 0; mt < 2; ++mt)
            #pragma unroll
            for (int h = 0; h < 2; ++h) {
                float v = rmin[mt][h];
                v = fminf(v, __shfl_xor_sync(0xffffffffu, v, 1));
                v = fminf(v, __shfl_xor_sync(0xffffffffu, v, 2));
                rmin[mt][h] = v;
            }
        if (r == 0) {
            #pragma unroll
            for (int mt = 0; mt < 2; ++mt)
                #pragma unroll
                for (int h = 0; h < 2; ++h) {
                    const int row = mbase + mt * 16 + h * 8 + q;
                    const float v = rmin[mt][h] + sssq[row];
                    atomicMin(&sdmin[row], __float_as_int(v));
                }
        }
        __syncthreads();

        // ---- fold into global; reset own slot ----
        if (tid < S_) {
            const int v = sdmin[tid];
            atomicMin(reinterpret_cast<int*>(out_dist) + b * S_ + tid, v);
            sdmin[tid] = 0x7F800000;
        }
    }
}

// ---------------------------------------------------------------------------
// Kernel 2: MLP, 256 blocks = 32 batches x 8 neuron groups of 64.
// Layer-2 partial class sums folded with atomicAdd (out_cls pre-zeroed).
// ---------------------------------------------------------------------------
__global__ __launch_bounds__(128) void mlp_kernel(
    const float* __restrict__ dist,
    const float* __restrict__ W1,
    const float* __restrict__ b1,
    const float* __restrict__ W2,
    const float* __restrict__ b2,
    float* __restrict__ out_cls)
{
    __shared__ float hsh[64];
    const int gb   = blockIdx.x;
    const int b    = gb >> 3;        // batch
    const int grp  = gb & 7;         // neuron group: [grp*64, grp*64+64)
    const int tid  = threadIdx.x;    // 128 threads = 4 warps
    const int wid  = tid >> 5;
    const int lane = tid & 31;

    // lane-resident distance float4 (L2-hot)
    const float4 d4 = reinterpret_cast<const float4*>(dist + b * S_)[lane];

    // Layer 1: warp w computes 16 neurons, coalesced LDG.128 per neuron
    #pragma unroll 4
    for (int i = 0; i < 16; ++i) {
        const int hloc = wid * 16 + i;
        const int h    = grp * 64 + hloc;
        const float4 w4 = reinterpret_cast<const float4*>(W1 + h * S_)[lane];
        float acc = d4.x * w4.x;
        acc = fmaf(d4.y, w4.y, acc);
        acc = fmaf(d4.z, w4.z, acc);
        acc = fmaf(d4.w, w4.w, acc);
        #pragma unroll
        for (int off = 16; off > 0; off >>= 1)
            acc += __shfl_xor_sync(0xffffffffu, acc, off);
        if (lane == 0) hsh[hloc] = fmaxf(acc + b1[h], 0.f);
    }
    __syncthreads();

    // Layer 2 partials over this group's 64 h values
    const float h0 = hsh[lane];
    const float h1 = hsh[lane + 32];
    for (int c = wid; c < C_; c += 4) {
        const float* w2r = W2 + c * H_ + grp * 64;
        float acc = h0 * w2r[lane];
        acc = fmaf(h1, w2r[lane + 32], acc);
        #pragma unroll
        for (int off = 16; off > 0; off >>= 1)
            acc += __shfl_xor_sync(0xffffffffu, acc, off);
        if (lane == 0) atomicAdd(out_cls + b * C_ + c, acc);
    }

    // bias added once per batch (group 0)
    if (grp == 0 && tid < C_)
        atomicAdd(out_cls + b * C_ + tid, b2[tid]);
}

// ---------------------------------------------------------------------------
extern "C" void kernel_launch(void* const* d_in, const int* in_sizes, int n_in,
                              void* d_out, int out_size)
{
    const float* x  = (const float*)d_in[0];
    const float* sh = (const float*)d_in[1];
    const float* W1 = (const float*)d_in[2];
    const float* b1 = (const float*)d_in[3];
    const float* W2 = (const float*)d_in[4];
    const float* b2 = (const float*)d_in[5];

    float* out_dist = (float*)d_out;
    float* out_cls  = (float*)d_out + B_ * S_;

    // distances -> huge positive sentinel; classes -> 0 (accumulated into)
    cudaMemsetAsync(out_dist, 0x7f, B_ * S_ * sizeof(float), 0);
    cudaMemsetAsync(out_cls, 0, B_ * C_ * sizeof(float), 0);

    dist_kernel<<<GRID, THR>>>(x, sh, out_dist);
    mlp_kernel<<<B_ * 8, 128>>>(out_dist, W1, b1, W2, b2, out_cls);
}

// round 10
// speedup vs baseline: 1.1156x; 1.0279x over previous
#include <cuda_runtime.h>
#include <cuda_fp16.h>
#include <cstdint>

// ---------------------------------------------------------------------------
// Problem constants
// ---------------------------------------------------------------------------
#define B_  32
#define D_  3
#define T_  16384
#define S_  128
#define L_  16
#define H_  512
#define C_  10
#define TP  16369          // T - L + 1 valid positions
#define SHN 48             // D*L = K (3 k-steps of 16)

#define NT      256        // positions per block tile (two 128-col MMA halves)
#define NTILES  (B_ * (T_ / NT))   // 2048
#define THR     256
#define GRID    293        // ceil(2048/7): balanced 7 tiles/block, 1 wave
#define XT_W    (NT + L_)  // 272 elements per x row in tile

#define INF_F __int_as_float(0x7F800000)

// ---------------------------------------------------------------------------
// D(16x8) += A(16x16,row) * B(16x8,col)   f16 x f16 -> f32
__device__ __forceinline__ void mma16(float* d, uint32_t a0, uint32_t a1,
                                      uint32_t a2, uint32_t a3,
                                      uint32_t b0, uint32_t b1) {
    asm volatile(
        "mma.sync.aligned.m16n8k16.row.col.f32.f16.f16.f32 "
        "{%0,%1,%2,%3}, {%4,%5,%6,%7}, {%8,%9}, {%0,%1,%2,%3};"
        : "+f"(d[0]), "+f"(d[1]), "+f"(d[2]), "+f"(d[3])
        : "r"(a0), "r"(a1), "r"(a2), "r"(a3), "r"(b0), "r"(b1));
}

__device__ __forceinline__ uint32_t packh2(float lo, float hi) {
    __half2 h = __floats2half2_rn(lo, hi);
    return *reinterpret_cast<uint32_t*>(&h);
}

// ---------------------------------------------------------------------------
// Kernel 1: persistent fp16-MMA shapelet distance (256-pos tiles, 2 halves)
// ---------------------------------------------------------------------------
__global__ __launch_bounds__(THR, 2) void dist_kernel(
    const float* __restrict__ x,
    const float* __restrict__ shg,
    float* __restrict__ out_dist)
{
    __shared__ float  xs[D_ * XT_W];        // raw fp32 (for exact wsq)
    __shared__ __half hA[D_ * XT_W];        // hA[i] = f16(x[i])   (even-pair copy)
    __shared__ __half hB[D_ * XT_W];        // hB[i] = f16(x[i+1]) (odd-pair copy)
    __shared__ float  swsq[NT];
    __shared__ float  sssq[S_];
    __shared__ int    sdmin[S_];

    const int tid  = threadIdx.x;
    const int wid  = tid >> 5;
    const int lane = tid & 31;
    const int q    = lane >> 2;      // groupID
    const int r    = lane & 3;       // threadID_in_group

    const int mbase = (wid & 3) * 32;       // warp's 32 M-rows
    const int nbase = (wid >> 2) * 64;      // warp's 64 N-cols (per half)

    // --- one-time: exact fp32 shapelet squared norms; A fragments -> regs ---
    if (tid < S_) {
        const float* srow = shg + tid * SHN;
        float ssq = 0.f;
        #pragma unroll
        for (int k = 0; k < SHN; ++k) ssq = fmaf(srow[k], srow[k], ssq);
        sssq[tid] = ssq;
        sdmin[tid] = 0x7F800000;
    }

    // A fragments: afr[ks][mt][4]; k = ks*16 + kk  (tile-invariant)
    uint32_t afr[3][2][4];
    #pragma unroll
    for (int ks = 0; ks < 3; ++ks) {
        #pragma unroll
        for (int mt = 0; mt < 2; ++mt) {
            const int r0 = mbase + mt * 16 + q;       // row for a0/a2
            const int r1 = r0 + 8;                    // row for a1/a3
            const int k0 = ks * 16 + 2 * r;
            const float* p0 = shg + r0 * SHN + k0;
            const float* p1 = shg + r1 * SHN + k0;
            afr[ks][mt][0] = packh2(-2.f * p0[0], -2.f * p0[1]);
            afr[ks][mt][1] = packh2(-2.f * p1[0], -2.f * p1[1]);
            afr[ks][mt][2] = packh2(-2.f * p0[8], -2.f * p0[9]);
            afr[ks][mt][3] = packh2(-2.f * p1[8], -2.f * p1[9]);
        }
    }
    __syncthreads();

    const uint32_t* hA32 = reinterpret_cast<const uint32_t*>(hA);
    const uint32_t* hB32 = reinterpret_cast<const uint32_t*>(hB);
    const uint32_t* hw = (q & 1) ? hB32 : hA32;
    const int lane_off = q + 2 * r - (q & 1);

    for (int tile = blockIdx.x; tile < NTILES; tile += GRID) {
        const int b     = tile >> 6;                  // 64 tiles / batch
        const int tbase = (tile & 63) * NT;
        const float* xb = x + (size_t)b * D_ * T_;

        // ---- phase 1: load x tile (fp32 + two fp16 copies), 204 float4 ----
        {
            const int idx4 = tid;
            if (idx4 < (D_ * XT_W) / 4) {             // 204
                const int d = idx4 / (XT_W / 4);      // XT_W/4 = 68
                const int j = (idx4 % (XT_W / 4)) * 4;
                const int g = tbase + j;
                float4 v;
                if (g + 3 < T_) {
                    v = *reinterpret_cast<const float4*>(xb + d * T_ + g);
                } else {
                    v.x = (g     < T_) ? xb[d*T_ + g]     : 0.f;
                    v.y = (g + 1 < T_) ? xb[d*T_ + g + 1] : 0.f;
                    v.z = (g + 2 < T_) ? xb[d*T_ + g + 2] : 0.f;
                    v.w = (g + 3 < T_) ? xb[d*T_ + g + 3] : 0.f;
                }
                *reinterpret_cast<float4*>(&xs[d * XT_W + j]) = v;
                const int hi = d * XT_W + j;
                *reinterpret_cast<uint32_t*>(&hA[hi])     = packh2(v.x, v.y);
                *reinterpret_cast<uint32_t*>(&hA[hi + 2]) = packh2(v.z, v.w);
                if (j > 0) hB[hi - 1] = __float2half(v.x);
                hB[hi    ] = __float2half(v.y);
                hB[hi + 1] = __float2half(v.z);
                hB[hi + 2] = __float2half(v.w);
            }
        }
        __syncthreads();

        // ---- phase 2: wsq, one position per thread (all 256) ----
        {
            float w0 = 0.f, w1 = 0.f, w2 = 0.f;
            #pragma unroll
            for (int l = 0; l < L_; ++l) {
                const float v0 = xs[0 * XT_W + tid + l];
                const float v1 = xs[1 * XT_W + tid + l];
                const float v2 = xs[2 * XT_W + tid + l];
                w0 = fmaf(v0, v0, w0);
                w1 = fmaf(v1, v1, w1);
                w2 = fmaf(v2, v2, w2);
            }
            swsq[tid] = (tbase + tid < TP) ? (w0 + w1 + w2) : INF_F;
        }
        __syncthreads();   // wsq ready for all epilogue readers

        // ---- phases 3+4: two N-halves of MMA + local epilogue ----
        float rmin[2][2];
        #pragma unroll
        for (int mt = 0; mt < 2; ++mt)
            #pragma unroll
            for (int h = 0; h < 2; ++h) rmin[mt][h] = INF_F;

        #pragma unroll
        for (int half = 0; half < 2; ++half) {
            const int nbh = half * 128 + nbase;

            float acc[2][8][4];
            #pragma unroll
            for (int mt = 0; mt < 2; ++mt)
                #pragma unroll
                for (int nt = 0; nt < 8; ++nt)
                    #pragma unroll
                    for (int e = 0; e < 4; ++e) acc[mt][nt][e] = 0.f;

            #pragma unroll
            for (int ks = 0; ks < 3; ++ks) {
                const int base = (ks * XT_W + nbh + lane_off) >> 1;
                #pragma unroll
                for (int nt = 0; nt < 8; ++nt) {
                    const uint32_t b0 = hw[base + nt * 4];
                    const uint32_t b1 = hw[base + nt * 4 + 4];
                    mma16(acc[0][nt], afr[ks][0][0], afr[ks][0][1],
                                      afr[ks][0][2], afr[ks][0][3], b0, b1);
                    mma16(acc[1][nt], afr[ks][1][0], afr[ks][1][1],
                                      afr[ks][1][2], afr[ks][1][3], b0, b1);
                }
            }

            float wq[8][2];
            #pragma unroll
            for (int nt = 0; nt < 8; ++nt) {
                wq[nt][0] = swsq[nbh + nt * 8 + r * 2    ];
                wq[nt][1] = swsq[nbh + nt * 8 + r * 2 + 1];
            }
            #pragma unroll
            for (int mt = 0; mt < 2; ++mt)
                #pragma unroll
                for (int h = 0; h < 2; ++h) {
                    float m = rmin[mt][h];
                    #pragma unroll
                    for (int nt = 0; nt < 8; ++nt) {
                        m = fminf(m, acc[mt][nt][h * 2    ] + wq[nt][0]);
                        m = fminf(m, acc[mt][nt][h * 2 + 1] + wq[nt][1]);
                    }
                    rmin[mt][h] = m;
                }
        }

        // ---- reduce: quad shfl + smem atomic (once per 256 positions) ----
        #pragma unroll
        for (int mt = 0; mt < 2; ++mt)
            #pragma unroll
            for (int h = 0; h < 2; ++h) {
                float v = rmin[mt][h];
                v = fminf(v, __shfl_xor_sync(0xffffffffu, v, 1));
                v = fminf(v, __shfl_xor_sync(0xffffffffu, v, 2));
                rmin[mt][h] = v;
            }
        if (r == 0) {
            #pragma unroll
            for (int mt = 0; mt < 2; ++mt)
                #pragma unroll
                for (int h = 0; h < 2; ++h) {
                    const int row = mbase + mt * 16 + h * 8 + q;
                    const float v = rmin[mt][h] + sssq[row];
                    atomicMin(&sdmin[row], __float_as_int(v));
                }
        }
        __syncthreads();

        // ---- fold into global; reset own slot ----
        if (tid < S_) {
            const int v = sdmin[tid];
            atomicMin(reinterpret_cast<int*>(out_dist) + b * S_ + tid, v);
            sdmin[tid] = 0x7F800000;
        }
    }
}

// ---------------------------------------------------------------------------
// Kernel 2: MLP, 256 blocks = 32 batches x 8 neuron groups of 64.
// Layer-2 partial class sums folded with atomicAdd (out_cls pre-zeroed).
// ---------------------------------------------------------------------------
__global__ __launch_bounds__(128) void mlp_kernel(
    const float* __restrict__ dist,
    const float* __restrict__ W1,
    const float* __restrict__ b1,
    const float* __restrict__ W2,
    const float* __restrict__ b2,
    float* __restrict__ out_cls)
{
    __shared__ float hsh[64];
    const int gb   = blockIdx.x;
    const int b    = gb >> 3;        // batch
    const int grp  = gb & 7;         // neuron group: [grp*64, grp*64+64)
    const int tid  = threadIdx.x;    // 128 threads = 4 warps
    const int wid  = tid >> 5;
    const int lane = tid & 31;

    // lane-resident distance float4 (L2-hot)
    const float4 d4 = reinterpret_cast<const float4*>(dist + b * S_)[lane];

    // Layer 1: warp w computes 16 neurons, coalesced LDG.128 per neuron
    #pragma unroll 4
    for (int i = 0; i < 16; ++i) {
        const int hloc = wid * 16 + i;
        const int h    = grp * 64 + hloc;
        const float4 w4 = reinterpret_cast<const float4*>(W1 + h * S_)[lane];
        float acc = d4.x * w4.x;
        acc = fmaf(d4.y, w4.y, acc);
        acc = fmaf(d4.z, w4.z, acc);
        acc = fmaf(d4.w, w4.w, acc);
        #pragma unroll
        for (int off = 16; off > 0; off >>= 1)
            acc += __shfl_xor_sync(0xffffffffu, acc, off);
        if (lane == 0) hsh[hloc] = fmaxf(acc + b1[h], 0.f);
    }
    __syncthreads();

    // Layer 2 partials over this group's 64 h values
    const float h0 = hsh[lane];
    const float h1 = hsh[lane + 32];
    for (int c = wid; c < C_; c += 4) {
        const float* w2r = W2 + c * H_ + grp * 64;
        float acc = h0 * w2r[lane];
        acc = fmaf(h1, w2r[lane + 32], acc);
        #pragma unroll
        for (int off = 16; off > 0; off >>= 1)
            acc += __shfl_xor_sync(0xffffffffu, acc, off);
        if (lane == 0) atomicAdd(out_cls + b * C_ + c, acc);
    }

    // bias added once per batch (group 0)
    if (grp == 0 && tid < C_)
        atomicAdd(out_cls + b * C_ + tid, b2[tid]);
}

// ---------------------------------------------------------------------------
extern "C" void kernel_launch(void* const* d_in, const int* in_sizes, int n_in,
                              void* d_out, int out_size)
{
    const float* x  = (const float*)d_in[0];
    const float* sh = (const float*)d_in[1];
    const float* W1 = (const float*)d_in[2];
    const float* b1 = (const float*)d_in[3];
    const float* W2 = (const float*)d_in[4];
    const float* b2 = (const float*)d_in[5];

    float* out_dist = (float*)d_out;
    float* out_cls  = (float*)d_out + B_ * S_;

    // distances -> huge positive sentinel; classes -> 0 (accumulated into)
    cudaMemsetAsync(out_dist, 0x7f, B_ * S_ * sizeof(float), 0);
    cudaMemsetAsync(out_cls, 0, B_ * C_ * sizeof(float), 0);

    dist_kernel<<<GRID, THR>>>(x, sh, out_dist);
    mlp_kernel<<<B_ * 8, 128>>>(out_dist, W1, b1, W2, b2, out_cls);
}